// round 2
// baseline (speedup 1.0000x reference)
#include <cuda_runtime.h>
#include <math.h>

#define BB 32
#define TT 2048
#define NN 2048
#define DD 512
#define LL 256
#define TEE 1024
#define HH 8
#define HD 64
#define SPLITS 16

// ---------------- scratch ----------------
__device__ float g_k[(size_t)BB * NN * DD];     // 128 MB
__device__ float g_v[(size_t)BB * NN * DD];     // 128 MB
__device__ float g_pm[BB * SPLITS * DD];
__device__ float g_ps[BB * SPLITS * DD];
__device__ float g_m[BB * DD];
__device__ float g_z[BB * DD];
__device__ float g_attn[(size_t)BB * HH * HD * HD]; // 4 MB
__device__ float g_ss[BB * 2 * DD];

// ---------------- emb path: scale/shift ----------------
__global__ void k_emb(const float* __restrict__ emb, const float* __restrict__ We,
                      const float* __restrict__ be) {
    int b = blockIdx.x;
    __shared__ float se[TEE];
    int tid = threadIdx.x;
    for (int i = tid; i < TEE; i += 512) {
        float e = emb[b * TEE + i];
        se[i] = e / (1.f + __expf(-e));
    }
    __syncthreads();
    for (int o = tid; o < 2 * DD; o += 512) {
        float acc = be[o];
        #pragma unroll 4
        for (int i = 0; i < TEE; i++) acc += se[i] * We[i * (2 * DD) + o];
        g_ss[b * 2 * DD + o] = acc;
    }
}

// ---------------- LN(xf) + k/v projection, 8 rows/block ----------------
__global__ void __launch_bounds__(512, 2)
k_kv(const float* __restrict__ xf, const float* __restrict__ tg, const float* __restrict__ tb,
     const float* __restrict__ Wk, const float* __restrict__ bk,
     const float* __restrict__ Wv, const float* __restrict__ bv) {
    int blk = blockIdx.x;
    int b = blk / (NN / 8);
    int n0 = (blk % (NN / 8)) * 8;
    __shared__ float sx[8][LL];
    __shared__ float red[2][8][64];
    __shared__ float smean[8], srstd[8];
    int tid = threadIdx.x;
    const float* base = xf + ((size_t)b * NN + n0) * LL;
    for (int i = tid; i < 8 * LL; i += 512) sx[i / LL][i % LL] = base[i];
    __syncthreads();
    int r = tid >> 6, lane = tid & 63;
    float s = 0.f, s2 = 0.f;
    for (int j = lane; j < LL; j += 64) { float v = sx[r][j]; s += v; s2 += v * v; }
    red[0][r][lane] = s; red[1][r][lane] = s2;
    __syncthreads();
    for (int off = 32; off > 0; off >>= 1) {
        if (lane < off) {
            red[0][r][lane] += red[0][r][lane + off];
            red[1][r][lane] += red[1][r][lane + off];
        }
        __syncthreads();
    }
    if (tid < 8) {
        float m = red[0][tid][0] / LL;
        float var = red[1][tid][0] / LL - m * m;
        smean[tid] = m; srstd[tid] = rsqrtf(var + 1e-5f);
    }
    __syncthreads();
    for (int i = tid; i < 8 * LL; i += 512) {
        int rr = i / LL, j = i % LL;
        sx[rr][j] = (sx[rr][j] - smean[rr]) * srstd[rr] * tg[j] + tb[j];
    }
    __syncthreads();
    int d = tid;
    float ak[8], av[8];
    float bkd = bk[d], bvd = bv[d];
    #pragma unroll
    for (int rr = 0; rr < 8; rr++) { ak[rr] = bkd; av[rr] = bvd; }
    #pragma unroll 4
    for (int j = 0; j < LL; j++) {
        float wk = Wk[j * DD + d], wv = Wv[j * DD + d];
        #pragma unroll
        for (int rr = 0; rr < 8; rr++) {
            float xv = sx[rr][j];
            ak[rr] += xv * wk;
            av[rr] += xv * wv;
        }
    }
    size_t ob = ((size_t)b * NN + n0) * DD + d;
    #pragma unroll
    for (int rr = 0; rr < 8; rr++) {
        g_k[ob + (size_t)rr * DD] = ak[rr];
        g_v[ob + (size_t)rr * DD] = av[rr];
    }
}

// ---------------- k softmax stats: partial online (m, s) per (b, split, d) ----------------
__global__ void k_redk() {
    int b = blockIdx.x, sp = blockIdx.y;
    int d = threadIdx.x;
    size_t base = ((size_t)b * NN + sp * (NN / SPLITS)) * DD + d;
    float m = -1e30f, s = 0.f;
    for (int n = 0; n < NN / SPLITS; n++) {
        float v = g_k[base + (size_t)n * DD];
        if (v > m) { s = s * __expf(m - v) + 1.f; m = v; }
        else s += __expf(v - m);
    }
    g_pm[(b * SPLITS + sp) * DD + d] = m;
    g_ps[(b * SPLITS + sp) * DD + d] = s;
}

__global__ void k_comb() {
    int b = blockIdx.x, d = threadIdx.x;
    float m = -1e30f;
    for (int sp = 0; sp < SPLITS; sp++) m = fmaxf(m, g_pm[(b * SPLITS + sp) * DD + d]);
    float z = 0.f;
    for (int sp = 0; sp < SPLITS; sp++)
        z += g_ps[(b * SPLITS + sp) * DD + d] * __expf(g_pm[(b * SPLITS + sp) * DD + d] - m);
    g_m[b * DD + d] = m;
    g_z[b * DD + d] = z;
}

// ---------------- attn[b,h,d,l] = sum_n exp(k - m) * v / Z ----------------
__global__ void __launch_bounds__(256, 4)
k_attn() {
    int bh = blockIdx.x;
    int b = bh / HH, h = bh % HH;
    __shared__ float ek[32][HD], vv[32][HD], sm[HD], sz[HD];
    int tid = threadIdx.x;
    if (tid < 64) { sm[tid] = g_m[b * DD + h * 64 + tid]; sz[tid] = g_z[b * DD + h * 64 + tid]; }
    int l = tid & 63, dg = tid >> 6;
    float acc[16];
    #pragma unroll
    for (int i = 0; i < 16; i++) acc[i] = 0.f;
    for (int nt = 0; nt < NN; nt += 32) {
        __syncthreads();
        for (int i = tid; i < 32 * 64; i += 256) {
            int nn = i >> 6, dd = i & 63;
            size_t g = ((size_t)b * NN + nt + nn) * DD + h * 64 + dd;
            ek[nn][dd] = __expf(g_k[g] - sm[dd]);
            vv[nn][dd] = g_v[g];
        }
        __syncthreads();
        #pragma unroll 4
        for (int nn = 0; nn < 32; nn++) {
            float vl = vv[nn][l];
            #pragma unroll
            for (int i = 0; i < 16; i++) acc[i] += ek[nn][dg + 4 * i] * vl;
        }
    }
    #pragma unroll
    for (int i = 0; i < 16; i++) {
        int dd = dg + 4 * i;
        g_attn[((size_t)bh * 64 + dd) * 64 + l] = acc[i] / sz[dd];
    }
}

// ---------------- fused q / y / modulate / Wo / residual, 8 rows per block ----------------
__global__ void __launch_bounds__(512, 2)
k_main(const float* __restrict__ x, const float* __restrict__ ng, const float* __restrict__ nb,
       const float* __restrict__ Wq, const float* __restrict__ bq,
       const float* __restrict__ sg, const float* __restrict__ sb,
       const float* __restrict__ Wo, const float* __restrict__ bo,
       float* __restrict__ out) {
    int blk = blockIdx.x;
    int b = blk / (TT / 8);
    int t0 = (blk % (TT / 8)) * 8;
    __shared__ float sa[8][DD];
    __shared__ float sq[8][DD];
    __shared__ float red[2][8][64];
    __shared__ float smean[8], srstd[8];
    __shared__ float gmax[64], gsum[64];
    __shared__ float pred[64][8];
    int tid = threadIdx.x;
    int d = tid;
    size_t rowbase = ((size_t)b * TT + t0) * DD;
    float xr[8];
    #pragma unroll
    for (int rr = 0; rr < 8; rr++) { xr[rr] = x[rowbase + (size_t)rr * DD + d]; sa[rr][d] = xr[rr]; }
    __syncthreads();
    int r = tid >> 6, lane = tid & 63;
    // ---- LN(x) ----
    {
        float s = 0.f, s2 = 0.f;
        for (int j = lane; j < DD; j += 64) { float v = sa[r][j]; s += v; s2 += v * v; }
        red[0][r][lane] = s; red[1][r][lane] = s2;
        __syncthreads();
        for (int off = 32; off > 0; off >>= 1) {
            if (lane < off) {
                red[0][r][lane] += red[0][r][lane + off];
                red[1][r][lane] += red[1][r][lane + off];
            }
            __syncthreads();
        }
        if (tid < 8) {
            float m = red[0][tid][0] / DD;
            float var = red[1][tid][0] / DD - m * m;
            smean[tid] = m; srstd[tid] = rsqrtf(var + 1e-5f);
        }
        __syncthreads();
    }
    {
        float gd = ng[d], bd = nb[d];
        #pragma unroll
        for (int rr = 0; rr < 8; rr++)
            sa[rr][d] = (xr[rr] - smean[rr]) * srstd[rr] * gd + bd;
    }
    __syncthreads();
    // ---- q = LN(x) @ Wq + bq ----
    float acc[8];
    {
        float bqd = bq[d];
        #pragma unroll
        for (int rr = 0; rr < 8; rr++) acc[rr] = bqd;
        #pragma unroll 4
        for (int j = 0; j < DD; j++) {
            float w = Wq[j * DD + d];
            #pragma unroll
            for (int rr = 0; rr < 8; rr++) acc[rr] += sa[rr][j] * w;
        }
        #pragma unroll
        for (int rr = 0; rr < 8; rr++) sq[rr][d] = acc[rr];
    }
    __syncthreads();
    // ---- per-head softmax over hd=64: 64 groups (row, head), 8 threads each ----
    {
        int g = tid >> 3, kk = tid & 7;
        int rr = g >> 3, hh = g & 7;
        float m = -1e30f;
        for (int j = kk; j < 64; j += 8) m = fmaxf(m, sq[rr][hh * 64 + j]);
        pred[g][kk] = m;
        __syncthreads();
        if (kk == 0) {
            float mm = pred[g][0];
            #pragma unroll
            for (int i = 1; i < 8; i++) mm = fmaxf(mm, pred[g][i]);
            gmax[g] = mm;
        }
        __syncthreads();
        float mm = gmax[g];
        float ss = 0.f;
        for (int j = kk; j < 64; j += 8) ss += __expf(sq[rr][hh * 64 + j] - mm);
        pred[g][kk] = ss;
        __syncthreads();
        if (kk == 0) {
            float t = 0.f;
            #pragma unroll
            for (int i = 0; i < 8; i++) t += pred[g][i];
            gsum[g] = t;
        }
        __syncthreads();
    }
    int hh = d >> 6;
    #pragma unroll
    for (int rr = 0; rr < 8; rr++) {
        int g = rr * 8 + hh;
        sq[rr][d] = __expf(sq[rr][d] - gmax[g]) / gsum[g];
    }
    __syncthreads();
    // ---- y = q @ attn (per head 64x64) ----
    float ay[8];
    {
        int l = d & 63;
        const float* ap = g_attn + (size_t)(b * HH + hh) * 64 * 64 + l;
        #pragma unroll
        for (int rr = 0; rr < 8; rr++) ay[rr] = 0.f;
        #pragma unroll 4
        for (int dd = 0; dd < 64; dd++) {
            float a = ap[dd * 64];
            #pragma unroll
            for (int rr = 0; rr < 8; rr++) ay[rr] += sq[rr][hh * 64 + dd] * a;
        }
        #pragma unroll
        for (int rr = 0; rr < 8; rr++) sa[rr][d] = ay[rr];
    }
    __syncthreads();
    // ---- LN(y) ----
    {
        float s = 0.f, s2 = 0.f;
        for (int j = lane; j < DD; j += 64) { float v = sa[r][j]; s += v; s2 += v * v; }
        red[0][r][lane] = s; red[1][r][lane] = s2;
        __syncthreads();
        for (int off = 32; off > 0; off >>= 1) {
            if (lane < off) {
                red[0][r][lane] += red[0][r][lane + off];
                red[1][r][lane] += red[1][r][lane + off];
            }
            __syncthreads();
        }
        if (tid < 8) {
            float m = red[0][tid][0] / DD;
            float var = red[1][tid][0] / DD - m * m;
            smean[tid] = m; srstd[tid] = rsqrtf(var + 1e-5f);
        }
        __syncthreads();
    }
    // ---- modulate + silu ----
    {
        float sgd = sg[d], sbd = sb[d];
        float sc = 1.f + g_ss[b * 2 * DD + d];
        float sh = g_ss[b * 2 * DD + DD + d];
        #pragma unroll
        for (int rr = 0; rr < 8; rr++) {
            float hv = (ay[rr] - smean[rr]) * srstd[rr] * sgd + sbd;
            hv = hv * sc + sh;
            sa[rr][d] = hv / (1.f + __expf(-hv));
        }
    }
    __syncthreads();
    // ---- out = x + silu(h) @ Wo + bo ----
    {
        float bod = bo[d];
        #pragma unroll
        for (int rr = 0; rr < 8; rr++) acc[rr] = bod;
        #pragma unroll 4
        for (int j = 0; j < DD; j++) {
            float w = Wo[j * DD + d];
            #pragma unroll
            for (int rr = 0; rr < 8; rr++) acc[rr] += sa[rr][j] * w;
        }
        #pragma unroll
        for (int rr = 0; rr < 8; rr++)
            out[rowbase + (size_t)rr * DD + d] = xr[rr] + acc[rr];
    }
}

extern "C" void kernel_launch(void* const* d_in, const int* in_sizes, int n_in,
                              void* d_out, int out_size) {
    const float* x   = (const float*)d_in[0];
    const float* xf  = (const float*)d_in[1];
    const float* emb = (const float*)d_in[2];
    const float* ng  = (const float*)d_in[3];
    const float* nb  = (const float*)d_in[4];
    const float* tg  = (const float*)d_in[5];
    const float* tb  = (const float*)d_in[6];
    const float* Wq  = (const float*)d_in[7];
    const float* bq  = (const float*)d_in[8];
    const float* Wk  = (const float*)d_in[9];
    const float* bk  = (const float*)d_in[10];
    const float* Wv  = (const float*)d_in[11];
    const float* bv  = (const float*)d_in[12];
    const float* We  = (const float*)d_in[13];
    const float* be  = (const float*)d_in[14];
    const float* sg  = (const float*)d_in[15];
    const float* sb  = (const float*)d_in[16];
    const float* Wo  = (const float*)d_in[17];
    const float* bo  = (const float*)d_in[18];
    float* out = (float*)d_out;

    k_emb<<<BB, 512>>>(emb, We, be);
    k_kv<<<BB * (NN / 8), 512>>>(xf, tg, tb, Wk, bk, Wv, bv);
    k_redk<<<dim3(BB, SPLITS), DD>>>();
    k_comb<<<BB, DD>>>();
    k_attn<<<BB * HH, 256>>>();
    k_main<<<BB * (TT / 8), 512>>>(x, ng, nb, Wq, bq, sg, sb, Wo, bo, out);
}